// round 17
// baseline (speedup 1.0000x reference)
#include <cuda_runtime.h>
#include <math.h>
#include <stdint.h>

#define B_ROWS 2048
#define D_DIM  512
#define C_CLS  32768
#define S_SCALE 64.0f
#define SQRT_S 8.0f
#define MARGIN  0.5f
#define EPS_CLIP 1e-7f

#define BM 128
#define BN 128
#define NCH 4                    // 4 k-chunks of 128 B per tile
#define CHUNK_BYTES 16384        // one operand chunk: 128 rows x 128 B
#define TILE_BYTES  65536        // 4 chunks
#define BUF_BYTES 32768          // A 16KB + B 16KB per stage
#define B_REGION  16384
#define MB_OFF    65536
#define SMEM_TOTAL (2 * BUF_BYTES + 128)

#define N_TILES_N 256
#define NTILES    4096
#define GRIDP     296            // persistent CTAs (2/SM on 148 SMs)

// prep grid split (8 warps = 8 rows per block)
#define PREP_W_BLOCKS  (C_CLS / 8)             // 4096
#define PREP_F_BLOCKS  (B_ROWS / 8)            // 256
#define PREP_T_BLOCKS  (B_ROWS / 8)            // 256
#define PREP_BLOCKS    (PREP_W_BLOCKS + PREP_F_BLOCKS + PREP_T_BLOCKS)

// ---------------------------------------------------------------------------
// Blocked + pre-swizzled e4m3 scratch:
//   g_F8: [16 tiles][4 chunks][128 rows][128 B], 16B col j stored at j^(row&7)
//   g_W8: [256 tiles][4 chunks][128 rows][128 B], same swizzle
__device__ float  g_rowsum[B_ROWS];
__device__ float  g_tgt[B_ROWS];
__device__ __align__(128) uint8_t g_F8[B_ROWS * D_DIM];
__device__ __align__(128) uint8_t g_W8[C_CLS * D_DIM];

// ---------------------------------------------------------------------------
__device__ __forceinline__ uint32_t smem_u32(const void* p) {
    uint32_t a;
    asm("{ .reg .u64 t; cvta.to.shared.u64 t, %1; cvt.u32.u64 %0, t; }" : "=r"(a) : "l"(p));
    return a;
}

__device__ __forceinline__ void mma_f8(float* c, const uint4& a,
                                       uint32_t b0, uint32_t b1) {
    asm volatile(
        "mma.sync.aligned.m16n8k32.row.col.f32.e4m3.e4m3.f32 "
        "{%0,%1,%2,%3}, {%4,%5,%6,%7}, {%8,%9}, {%0,%1,%2,%3};"
        : "+f"(c[0]), "+f"(c[1]), "+f"(c[2]), "+f"(c[3])
        : "r"(a.x), "r"(a.y), "r"(a.z), "r"(a.w), "r"(b0), "r"(b1));
}

__device__ __forceinline__ void ldsm4(uint4& d, uint32_t a) {
    asm volatile("ldmatrix.sync.aligned.m8n8.x4.shared.b16 {%0,%1,%2,%3}, [%4];"
                 : "=r"(d.x), "=r"(d.y), "=r"(d.z), "=r"(d.w) : "r"(a));
}

__device__ __forceinline__ void bulkcp(uint32_t dst, const void* src,
                                       uint32_t bytes, uint32_t mbar) {
    asm volatile(
        "cp.async.bulk.shared::cluster.global.mbarrier::complete_tx::bytes "
        "[%0], [%1], %2, [%3];"
        :: "r"(dst), "l"(src), "r"(bytes), "r"(mbar) : "memory");
}
#define MBAR_INIT(bar, cnt) \
    asm volatile("mbarrier.init.shared.b64 [%0], %1;" :: "r"(bar), "r"(cnt) : "memory")
#define MBAR_EXPECT_TX(bar, bytes) \
    asm volatile("mbarrier.arrive.expect_tx.shared.b64 _, [%0], %1;" :: "r"(bar), "r"(bytes) : "memory")
__device__ __forceinline__ void mbar_wait(uint32_t bar, uint32_t parity) {
    asm volatile(
        "{\n\t.reg .pred P;\n\t"
        "W%=:\n\t"
        "mbarrier.try_wait.parity.acquire.cta.shared::cta.b64 P, [%0], %1, 0x989680;\n\t"
        "@P bra D%=;\n\t"
        "bra W%=;\n\t"
        "D%=:\n\t}"
        :: "r"(bar), "r"(parity) : "memory");
}

__device__ __forceinline__ uint32_t pack_e4m3x2(float lo, float hi) {
    uint16_t r;
    asm("cvt.rn.satfinite.e4m3x2.f32 %0, %1, %2;" : "=h"(r) : "f"(hi), "f"(lo));
    return (uint32_t)r;
}
__device__ __forceinline__ uint32_t pack_e4m3x4(float a, float b, float c, float d) {
    return pack_e4m3x2(a, b) | (pack_e4m3x2(c, d) << 16);
}

// ---------------------------------------------------------------------------
// Fused prep -> blocked + pre-swizzled layout (proven R16).
__global__ void prep_kernel(const float* __restrict__ F,
                            const int* __restrict__ Y,
                            const float* __restrict__ W) {
    const int bid  = blockIdx.x;
    const int warp = threadIdx.x >> 5;
    const int lane = threadIdx.x & 31;

    if (bid < PREP_W_BLOCKS + PREP_F_BLOCKS) {
        const bool isW = bid < PREP_W_BLOCKS;
        int row = isW ? (bid * 8 + warp) : ((bid - PREP_W_BLOCKS) * 8 + warp);
        const float* src = isW ? W : F;
        if (!isW && lane == 0) g_rowsum[row] = 0.0f;
        const float4* p = (const float4*)(src + (size_t)row * D_DIM);
        float4 v[4]; float ss = 0.0f;
#pragma unroll
        for (int i = 0; i < 4; i++) {
            v[i] = p[lane + 32 * i];
            ss = fmaf(v[i].x, v[i].x, fmaf(v[i].y, v[i].y, fmaf(v[i].z, v[i].z, fmaf(v[i].w, v[i].w, ss))));
        }
#pragma unroll
        for (int o = 16; o; o >>= 1) ss += __shfl_xor_sync(0xffffffffu, ss, o);
        float sc = SQRT_S / fmaxf(sqrtf(ss), 1e-12f);
        uint32_t* o32 = (uint32_t*)(isW ? g_W8 : g_F8);
        const int tile = row >> 7, rr = row & 127;
        const size_t base = (size_t)tile * 16384 + (size_t)rr * 32;   // words
        const int sw = ((((lane >> 2) ^ (rr & 7)) << 2) | (lane & 3));
#pragma unroll
        for (int i = 0; i < 4; i++)
            o32[base + (size_t)i * 4096 + sw] =
                pack_e4m3x4(v[i].x * sc, v[i].y * sc, v[i].z * sc, v[i].w * sc);
    } else {
        int row = (bid - PREP_W_BLOCKS - PREP_F_BLOCKS) * 8 + warp;
        int cls = Y[row];
        const float4* fp = (const float4*)(F + (size_t)row * D_DIM);
        const float4* wp = (const float4*)(W + (size_t)cls * D_DIM);
        float dot = 0.0f, ff = 0.0f, ww = 0.0f;
#pragma unroll
        for (int i = 0; i < 4; i++) {
            float4 a = fp[lane + 32 * i];
            float4 b = wp[lane + 32 * i];
            dot = fmaf(a.x, b.x, fmaf(a.y, b.y, fmaf(a.z, b.z, fmaf(a.w, b.w, dot))));
            ff  = fmaf(a.x, a.x, fmaf(a.y, a.y, fmaf(a.z, a.z, fmaf(a.w, a.w, ff))));
            ww  = fmaf(b.x, b.x, fmaf(b.y, b.y, fmaf(b.z, b.z, fmaf(b.w, b.w, ww))));
        }
#pragma unroll
        for (int o = 16; o; o >>= 1) {
            dot += __shfl_xor_sync(0xffffffffu, dot, o);
            ff  += __shfl_xor_sync(0xffffffffu, ff,  o);
            ww  += __shfl_xor_sync(0xffffffffu, ww,  o);
        }
        if (lane == 0)
            g_tgt[row] = dot / (fmaxf(sqrtf(ff), 1e-12f) * fmaxf(sqrtf(ww), 1e-12f));
    }
}

// ---------------------------------------------------------------------------
// Persistent fp8 mma GEMM: 296 CTAs, tiles bid + t*GRIDP. The 2-stage
// bulk-DMA + mbarrier ring runs continuously across tiles; prefetch is
// thread-0-only (2 UBLKCP per chunk). Mainloop identical to R16.
__global__ void __launch_bounds__(256, 2)
gemm_exp_mma_kernel() {
    extern __shared__ __align__(128) char smb[];
    const uint32_t smbase = smem_u32(smb);
    const int tid  = threadIdx.x;
    const int lane = tid & 31;
    const int warp = tid >> 5;
    const int wm = warp >> 2;          // 0..1
    const int wn = warp & 3;           // 0..3
    const int bid = blockIdx.x;

    const uint32_t mb = smbase + MB_OFF;
    if (tid == 0) { MBAR_INIT(mb, 1); MBAR_INIT(mb + 8, 1); }
    __syncthreads();

    const int myTiles = (NTILES - 1 - bid) / GRIDP + 1;
    const int total = myTiles * NCH;

    // ---- ldmatrix lane addressing (proven) ----
    const int l15 = lane & 15, xorl = lane & 7, hi = lane >> 4;
    uint32_t xk[4];
#pragma unroll
    for (int ks = 0; ks < 4; ks++)
        xk[ks] = (uint32_t)((((ks << 1) | hi) ^ xorl) << 4);
    const uint32_t aBase = smbase + ((wm * 64 + l15) << 7);
    const uint32_t bBase = smbase + B_REGION + ((wn * 32 + l15) << 7);

    // thread-0 prefetch of global chunk g2 into stage g2&1
    auto prefetch = [&](int g2) {
        const int ti = g2 >> 2, c2 = g2 & 3;
        const int tile = bid + ti * GRIDP;
        const uint8_t* pa = g_F8 + (size_t)(tile >> 8) * TILE_BYTES + (size_t)c2 * CHUNK_BYTES;
        const uint8_t* pb = g_W8 + (size_t)(tile & 255) * TILE_BYTES + (size_t)c2 * CHUNK_BYTES;
        const uint32_t st  = smbase + (uint32_t)(g2 & 1) * BUF_BYTES;
        const uint32_t bar = mb + (uint32_t)(g2 & 1) * 8;
        MBAR_EXPECT_TX(bar, BUF_BYTES);
        bulkcp(st,            pa, CHUNK_BYTES, bar);
        bulkcp(st + B_REGION, pb, CHUNK_BYTES, bar);
    };

    if (tid == 0) { prefetch(0); prefetch(1); }

    int g = 0;
#pragma unroll 1
    for (int t = 0; t < myTiles; t++) {
        const int tile = bid + t * GRIDP;
        const int tm = tile >> 8;

        float acc[4][4][4];
#pragma unroll
        for (int a = 0; a < 4; a++)
#pragma unroll
            for (int b = 0; b < 4; b++)
#pragma unroll
                for (int c = 0; c < 4; c++) acc[a][b][c] = 0.0f;

#pragma unroll
        for (int c = 0; c < NCH; c++, g++) {
            mbar_wait(mb + (g & 1) * 8, (g >> 1) & 1);
            const uint32_t bo = (uint32_t)(g & 1) * BUF_BYTES;
#pragma unroll
            for (int ks = 0; ks < 4; ks++) {
                uint4 afr[4], b0, b1;
#pragma unroll
                for (int mt = 0; mt < 4; mt++)
                    ldsm4(afr[mt], aBase + bo + (mt << 11) + xk[ks]);
                ldsm4(b0, bBase + bo + xk[ks]);
                ldsm4(b1, bBase + bo + (1 << 11) + xk[ks]);
#pragma unroll
                for (int mt = 0; mt < 4; mt++) {
                    mma_f8(acc[mt][0], afr[mt], b0.x, b0.z);
                    mma_f8(acc[mt][1], afr[mt], b0.y, b0.w);
                    mma_f8(acc[mt][2], afr[mt], b1.x, b1.z);
                    mma_f8(acc[mt][3], afr[mt], b1.y, b1.w);
                }
            }
            if (g + 2 < total) {
                __syncthreads();          // all warps done reading stage g&1
                if (tid == 0) prefetch(g + 2);
            }
        }

        // ---- per-tile epilogue (overlaps in-flight DMA of next tile) ----
        float s[4][2];
#pragma unroll
        for (int mt = 0; mt < 4; mt++) {
            float s0 = 0.0f, s1 = 0.0f;
#pragma unroll
            for (int nt = 0; nt < 4; nt++) {
                s0 += __expf(acc[mt][nt][0]) + __expf(acc[mt][nt][1]);
                s1 += __expf(acc[mt][nt][2]) + __expf(acc[mt][nt][3]);
            }
            s[mt][0] = s0; s[mt][1] = s1;
        }
#pragma unroll
        for (int o = 1; o < 4; o <<= 1)
#pragma unroll
            for (int mt = 0; mt < 4; mt++) {
                s[mt][0] += __shfl_xor_sync(0xffffffffu, s[mt][0], o);
                s[mt][1] += __shfl_xor_sync(0xffffffffu, s[mt][1], o);
            }
        if ((lane & 3) == 0) {
            int gg = lane >> 2;
            int base = tm * BM + wm * 64 + gg;
#pragma unroll
            for (int mt = 0; mt < 4; mt++) {
                atomicAdd(&g_rowsum[base + mt * 16],     s[mt][0]);
                atomicAdd(&g_rowsum[base + mt * 16 + 8], s[mt][1]);
            }
        }
    }
}

// ---------------------------------------------------------------------------
__global__ void loss_kernel(float* __restrict__ out) {
    __shared__ double sh[1024];
    double a = 0.0;
    for (int b = threadIdx.x; b < B_ROWS; b += blockDim.x) {
        float t = fminf(fmaxf(g_tgt[b], -1.0f + EPS_CLIP), 1.0f - EPS_CLIP);
        float num = S_SCALE * cosf(acosf(t) + MARGIN);
        float excl = g_rowsum[b] - __expf(S_SCALE * t);
        double denom = (double)__expf(num) + (double)excl;
        a += (double)num - log(denom);
    }
    sh[threadIdx.x] = a;
    __syncthreads();
    for (int s = 512; s > 0; s >>= 1) {
        if (threadIdx.x < s) sh[threadIdx.x] += sh[threadIdx.x + s];
        __syncthreads();
    }
    if (threadIdx.x == 0) out[0] = (float)(-sh[0] / (double)B_ROWS);
}

// ---------------------------------------------------------------------------
extern "C" void kernel_launch(void* const* d_in, const int* in_sizes, int n_in,
                              void* d_out, int out_size) {
    const float* F = (const float*)d_in[0];
    const int*   Y = (const int*)d_in[1];
    const float* W = (const float*)d_in[2];
    float* out = (float*)d_out;

    cudaFuncSetAttribute(gemm_exp_mma_kernel,
                         cudaFuncAttributeMaxDynamicSharedMemorySize, SMEM_TOTAL);

    prep_kernel<<<PREP_BLOCKS, 256>>>(F, Y, W);

    gemm_exp_mma_kernel<<<GRIDP, 256, SMEM_TOTAL>>>();

    loss_kernel<<<1, 1024>>>(out);
}